// round 12
// baseline (speedup 1.0000x reference)
#include <cuda_runtime.h>
#include <math.h>

// Per-run published data (indexed slots -> deterministic) + per-batch counters.
// 32768 runs max (B*S/16), 128 batches. All zero-init; counters self-reset.
__device__ float2 g_part[32768];
__device__ float2 g_head[32768];
__device__ float2 g_tail[32768];
__device__ int    g_cnt[128];

#define RUN_ROWS 16            // rows per run (2 octets)
#define DOUT     64

// ---------------------------------------------------------------------------
// Warp-autonomous fused kernel. No __syncthreads anywhere.
// Each warp: grid-stride over 16-row runs; t kept in registers; in-run diffs
// inline; per-run publish (part/head/tail + release + counter). 256th arrival
// per batch finalizes that batch at warp level.
// ---------------------------------------------------------------------------
__global__ __launch_bounds__(256, 2)
void k_all(const float* __restrict__ x,
           const float* __restrict__ w1,
           const float* __restrict__ b1,
           const float* __restrict__ w2,
           const float* __restrict__ b2,
           const float* __restrict__ w3,
           const float* __restrict__ b3,
           float* __restrict__ out,
           int rows, int S)
{
    const int tid    = threadIdx.x;
    const int lane   = tid & 31;
    const int q      = lane & 3;            // column slice within quad
    const int sub    = lane >> 2;           // row within octet (0..7)
    const int gwarp  = blockIdx.x * (blockDim.x >> 5) + (tid >> 5);
    const int nwarps = gridDim.x * (blockDim.x >> 5);

    const int nruns = rows / RUN_ROWS;      // 32768
    const int rpb   = S / RUN_ROWS;         // 256 runs per batch

    const float4* __restrict__ X = reinterpret_cast<const float4*>(x);
    const float4* __restrict__ W = reinterpret_cast<const float4*>(w1);

    // lane-local weight slices (proven quad-map layout)
    float4 wa0[8], wa1[8];
    #pragma unroll
    for (int k = 0; k < 8; ++k) { wa0[k] = W[q + 4*k]; wa1[k] = W[32 + q + 4*k]; }
    const float bb0 = b1[0], bb1 = b1[1];
    const float c0 = w2[0], c1 = w2[1], cb = b2[0];

    for (int run = gwarp; run < nruns; run += nwarps) {
        const int R0 = run * RUN_ROWS;

        // ---- two octets, proven 8-deep LDG.128 quad-map pattern ----
        float tA, tB;
        #pragma unroll
        for (int half = 0; half < 2; ++half) {
            const size_t base = (size_t)(R0 + half * 8 + sub) * 32 + q;
            float4 v[8];
            #pragma unroll
            for (int k = 0; k < 8; ++k) v[k] = X[base + 4*k];

            float d0 = 0.f, d1 = 0.f;
            #pragma unroll
            for (int k = 0; k < 8; ++k) {
                d0 += v[k].x*wa0[k].x + v[k].y*wa0[k].y + v[k].z*wa0[k].z + v[k].w*wa0[k].w;
                d1 += v[k].x*wa1[k].x + v[k].y*wa1[k].y + v[k].z*wa1[k].z + v[k].w*wa1[k].w;
            }
            d0 += __shfl_xor_sync(0xffffffffu, d0, 1);
            d0 += __shfl_xor_sync(0xffffffffu, d0, 2);
            d1 += __shfl_xor_sync(0xffffffffu, d1, 1);
            d1 += __shfl_xor_sync(0xffffffffu, d1, 2);

            float h0 = fmaxf(d0 + bb0, 0.0f);
            float h1 = fmaxf(d1 + bb1, 0.0f);
            float t  = fmaf(c1, h1, fmaf(c0, h0, cb));   // all lanes of quad hold it
            if (half == 0) tA = t; else tB = t;
        }

        // ---- assemble t[R0+l] in lane l (l<16); idx (4l)&31 works for both ----
        const int idx = (4 * lane) & 31;
        const float sa = __shfl_sync(0xffffffffu, tA, idx);
        const float sb = __shfl_sync(0xffffffffu, tB, idx);
        const float tf = (lane < 8) ? sa : sb;
        const float t2 = __shfl_down_sync(0xffffffffu, tf, 2);

        // ---- 14 in-run diffs: i = R0+l, l = 0..13 (always valid) ----
        float fs = 0.f, fss = 0.f;
        if (lane < 14) {
            float l = logf(fabsf(t2 - tf) + 1e-6f);
            fs = l; fss = l * l;
        }
        #pragma unroll
        for (int off = 16; off; off >>= 1) {
            fs  += __shfl_xor_sync(0xffffffffu, fs,  off);
            fss += __shfl_xor_sync(0xffffffffu, fss, off);
        }

        // head/tail t pairs for cross-run boundary diffs (done by finalizer)
        const float h0v = __shfl_sync(0xffffffffu, tf, 0);
        const float h1v = __shfl_sync(0xffffffffu, tf, 1);
        const float e0v = __shfl_sync(0xffffffffu, tf, 14);
        const float e1v = __shfl_sync(0xffffffffu, tf, 15);

        const int b = run / rpb;
        int last = 0;
        if (lane == 0) {
            g_part[run] = make_float2(fs, fss);
            g_head[run] = make_float2(h0v, h1v);
            g_tail[run] = make_float2(e0v, e1v);
            __threadfence();                             // release our slots
            last = (atomicAdd(&g_cnt[b], 1) == rpb - 1) ? 1 : 0;
        }
        last = __shfl_sync(0xffffffffu, last, 0);

        // ---- warp-level finalize of batch b ----
        if (last) {
            __threadfence();                             // acquire all slots
            const int r0 = b * rpb;

            // fixed-order partial sums: lane reads runs [lane*8, lane*8+8)
            double s = 0.0, ss = 0.0;
            #pragma unroll
            for (int k = 0; k < 8; ++k) {
                float2 p = g_part[r0 + lane * 8 + k];
                s += (double)p.x; ss += (double)p.y;
            }
            // boundary diffs: boundaries k = 0..rpb-2 (2 diffs each)
            for (int k = lane; k < rpb - 1; k += 32) {
                float2 tl = g_tail[r0 + k];
                float2 hd = g_head[r0 + k + 1];
                float l1 = logf(fabsf(hd.x - tl.x) + 1e-6f);
                float l2 = logf(fabsf(hd.y - tl.y) + 1e-6f);
                s  += (double)l1 + (double)l2;
                ss += (double)l1 * l1 + (double)l2 * l2;
            }
            #pragma unroll
            for (int off = 16; off; off >>= 1) {
                s  += __shfl_xor_sync(0xffffffffu, s,  off);
                ss += __shfl_xor_sync(0xffffffffu, ss, off);
            }
            const double Nd = (double)(S - 2);
            double mean = s / Nd;
            double var  = (ss - s * s / Nd) / (Nd - 1.0);
            if (var < 0.0) var = 0.0;
            const float m  = (float)mean;
            const float sd = (float)sqrt(var);

            // head: lane computes outputs lane and lane+32
            const float o1 = tanhf(m * w3[2*lane]        + sd * w3[2*lane + 1]        + b3[lane]);
            const float o2 = tanhf(m * w3[2*(lane+32)]   + sd * w3[2*(lane+32) + 1]   + b3[lane + 32]);

            // broadcast output: DOUT identical rows of DOUT floats
            float* __restrict__ ob = out + (size_t)b * DOUT * DOUT;
            #pragma unroll 4
            for (int r = 0; r < DOUT; ++r) {
                ob[r * DOUT + lane]      = o1;
                ob[r * DOUT + lane + 32] = o2;
            }

            if (lane == 0) g_cnt[b] = 0;     // reset for next graph replay
        }
    }
}

extern "C" void kernel_launch(void* const* d_in, const int* in_sizes, int n_in,
                              void* d_out, int out_size)
{
    const float* x  = (const float*)d_in[0];
    const float* w1 = (const float*)d_in[1];
    const float* b1 = (const float*)d_in[2];
    const float* w2 = (const float*)d_in[3];
    const float* b2 = (const float*)d_in[4];
    const float* w3 = (const float*)d_in[5];
    const float* b3 = (const float*)d_in[6];
    float* out = (float*)d_out;

    const int B    = out_size / (DOUT * DOUT);   // 128
    const int rows = in_sizes[0] / 128;          // B * S
    const int S    = rows / B;                   // 4096

    k_all<<<296, 256>>>(x, w1, b1, w2, b2, w3, b3, out, rows, S);
}

// round 13
// speedup vs baseline: 3.2952x; 3.2952x over previous
#include <cuda_runtime.h>
#include <math.h>

// ---------------------------------------------------------------------------
// One self-contained 512-thread block per batch (R9 skeleton).
//  Phase 1: stream x[b] (2MB) quad-mapped; t -> smem; 6/8 of the log-diffs
//           computed IN REGISTERS right after the butterfly (hidden under BW).
//  Phase 2: only the 1022 cross-octet boundary diffs + reduction + head.
// ---------------------------------------------------------------------------
__global__ __launch_bounds__(512, 1)
void k_all(const float* __restrict__ x,
           const float* __restrict__ w1,
           const float* __restrict__ b1,
           const float* __restrict__ w2,
           const float* __restrict__ b2,
           const float* __restrict__ w3,
           const float* __restrict__ b3,
           float* __restrict__ out,
           int S, int dout)
{
    extern __shared__ float t_sh[];          // S floats (16KB)
    __shared__ double sh_s[16], sh_ss[16];
    __shared__ alignas(16) float sh_stats[2];
    __shared__ alignas(16) float sh_o[64];

    const int b    = blockIdx.x;
    const int tid  = threadIdx.x;
    const int lane = tid & 31;
    const int q    = lane & 3;               // column slice within quad
    const int sub  = lane >> 2;              // row within octet (0..7)
    const int wid  = tid >> 5;               // 16 warps

    const float4* __restrict__ X = reinterpret_cast<const float4*>(x);
    const float4* __restrict__ W = reinterpret_cast<const float4*>(w1);

    float fs = 0.f, fss = 0.f;               // per-thread in-stream diff partials

    // ---- Phase 1: stream (quad mapping; t on ALL lanes; 6 in-octet diffs) ----
    {
        float4 wa0[8], wa1[8];
        #pragma unroll
        for (int k = 0; k < 8; ++k) { wa0[k] = W[q + 4*k]; wa1[k] = W[32 + q + 4*k]; }
        const float bb0 = b1[0], bb1 = b1[1];
        const float c0 = w2[0], c1 = w2[1], cb = b2[0];

        const int octets = S >> 3;           // 512
        for (int o = wid; o < octets; o += 16) {
            const int row = (o << 3) + sub;  // local row in batch
            const size_t base = ((size_t)b * S + row) * 32 + q;

            float4 v[8];
            #pragma unroll
            for (int k = 0; k < 8; ++k) v[k] = X[base + 4*k];

            float d0 = 0.f, d1 = 0.f;
            #pragma unroll
            for (int k = 0; k < 8; ++k) {
                d0 += v[k].x*wa0[k].x + v[k].y*wa0[k].y + v[k].z*wa0[k].z + v[k].w*wa0[k].w;
                d1 += v[k].x*wa1[k].x + v[k].y*wa1[k].y + v[k].z*wa1[k].z + v[k].w*wa1[k].w;
            }
            d0 += __shfl_xor_sync(0xffffffffu, d0, 1);
            d0 += __shfl_xor_sync(0xffffffffu, d0, 2);
            d1 += __shfl_xor_sync(0xffffffffu, d1, 1);
            d1 += __shfl_xor_sync(0xffffffffu, d1, 2);

            // t on ALL lanes (butterfly left full sums everywhere)
            const float h0 = fmaxf(d0 + bb0, 0.0f);
            const float h1 = fmaxf(d1 + bb1, 0.0f);
            const float t  = fmaf(c1, h1, fmaf(c0, h0, cb));

            if (q == 0) t_sh[row] = t;

            // in-octet diffs: t[row+2] lives at lane+8 (sub+2, same q)
            const float t2 = __shfl_down_sync(0xffffffffu, t, 8);
            if (q == 0 && sub < 6) {         // rows o*8 .. o*8+5 -> valid diffs
                const float l = logf(fabsf(t2 - t) + 1e-6f);
                fs += l;
                fss = fmaf(l, l, fss);
            }
        }
    }
    __syncthreads();

    // ---- Phase 2: boundary diffs only (i = 8k+6, 8k+7 < S-2) ----
    {
        const int nb2 = ((S >> 3) << 1);     // 1024 candidate boundary diffs
        for (int j = tid; j < nb2; j += 512) {
            const int i = ((j >> 1) << 3) + 6 + (j & 1);
            if (i < S - 2) {
                const float d = fabsf(t_sh[i + 2] - t_sh[i]);
                const float l = logf(d + 1e-6f);
                fs += l;
                fss = fmaf(l, l, fss);
            }
        }
    }

    // ---- reduction (identical math path to R9: float partials -> double) ----
    double s = (double)fs, ss = (double)fss;
    #pragma unroll
    for (int off = 16; off; off >>= 1) {
        s  += __shfl_xor_sync(0xffffffffu, s,  off);
        ss += __shfl_xor_sync(0xffffffffu, ss, off);
    }
    if (lane == 0) { sh_s[wid] = s; sh_ss[wid] = ss; }
    __syncthreads();
    if (wid == 0) {
        double ts  = (lane < 16) ? sh_s[lane]  : 0.0;
        double tss = (lane < 16) ? sh_ss[lane] : 0.0;
        #pragma unroll
        for (int off = 8; off; off >>= 1) {
            ts  += __shfl_xor_sync(0xffffffffu, ts,  off);
            tss += __shfl_xor_sync(0xffffffffu, tss, off);
        }
        if (lane == 0) {
            const double Nd = (double)(S - 2);
            double mean = ts / Nd;
            double var  = (tss - ts * ts / Nd) / (Nd - 1.0);
            if (var < 0.0) var = 0.0;
            sh_stats[0] = (float)mean;
            sh_stats[1] = (float)sqrt(var);
        }
    }
    __syncthreads();

    // ---- head + broadcast output ----
    if (tid < dout)
        sh_o[tid] = tanhf(sh_stats[0] * w3[2*tid] + sh_stats[1] * w3[2*tid + 1] + b3[tid]);
    __syncthreads();

    float4* __restrict__ ob = reinterpret_cast<float4*>(out + (size_t)b * dout * dout);
    const float4* __restrict__ so = reinterpret_cast<const float4*>(sh_o);
    const int total4 = (dout * dout) >> 2;   // 1024
    const int row4   = dout >> 2;            // 16
    for (int k = tid; k < total4; k += 512)
        ob[k] = so[k & (row4 - 1)];
}

extern "C" void kernel_launch(void* const* d_in, const int* in_sizes, int n_in,
                              void* d_out, int out_size)
{
    const float* x  = (const float*)d_in[0];
    const float* w1 = (const float*)d_in[1];
    const float* b1 = (const float*)d_in[2];
    const float* w2 = (const float*)d_in[3];
    const float* b2 = (const float*)d_in[4];
    const float* w3 = (const float*)d_in[5];
    const float* b3 = (const float*)d_in[6];
    float* out = (float*)d_out;

    const int DOUT = 64;
    const int B    = out_size / (DOUT * DOUT);   // 128
    const int rows = in_sizes[0] / 128;          // B * S
    const int S    = rows / B;                   // 4096

    k_all<<<B, 512, S * sizeof(float)>>>(x, w1, b1, w2, b2, w3, b3, out, S, DOUT);
}